// round 13
// baseline (speedup 1.0000x reference)
#include <cuda_runtime.h>
#include <cuda_bf16.h>
#include <cstdint>
#include <math.h>

// ---------------------------------------------------------------------------
// CorrelationAdaptor, fully batched: 7 launches (incl. profiling-shift dummy).
//   dummy -> wprep -> transpose_all(+copy) -> corr_all -> offset_all
//   -> im2col_all -> gemm_mma (mma.sync bf16 3-term split, 128x128 tiles)
// Levels: S={64,32,16,8}, disp={8,8,4,2}, stride={2,1,1,1}
// K2={289,289,81,25}, pad={16,8,4,2}, SP={320,320,96,32}
// Flat pixel space (2P per level): bases {0, 8192, 10240, 10752}, total 10880.
// NOTE: harness compiles .target sm_100 (no 'a') -> tcgen05 unavailable.
// ---------------------------------------------------------------------------

__device__ float g_xt  [5570560];                        // NHWC x, all levels
__device__ float g_corr[3330048];                        // [flat bp][SP]
__device__ float g_off [10880 * 72];                     // [flat p][72]
__device__ __align__(16) unsigned g_colh[10880 * 1152];  // bf16x2 col hi [p][K/2]
__device__ __align__(16) unsigned g_coll[10880 * 1152];  // bf16x2 col lo
__device__ __align__(16) unsigned g_wh  [4 * 256 * 1152];// bf16x2 W hi [l][o][K/2]
__device__ __align__(16) unsigned g_wl  [4 * 256 * 1152];// bf16x2 W lo
__device__ float g_dummy[32];

__device__ __forceinline__ uint32_t smem_u32(const void* p) {
    uint32_t a;
    asm("{ .reg .u64 t; cvta.to.shared.u64 t, %1; cvt.u32.u64 %0, t; }"
        : "=r"(a) : "l"(p));
    return a;
}

#define CPA16(dst, src) \
    asm volatile("cp.async.cg.shared.global [%0], [%1], 16;" \
                 :: "r"(dst), "l"(src))
#define CPA_COMMIT() asm volatile("cp.async.commit_group;" ::: "memory")
#define CPA_WAIT1()  asm volatile("cp.async.wait_group 1;" ::: "memory")
#define CPA_WAIT0()  asm volatile("cp.async.wait_group 0;" ::: "memory")

#define LDSM4(r, addr) \
    asm volatile("ldmatrix.sync.aligned.m8n8.x4.shared.b16 {%0,%1,%2,%3}, [%4];" \
                 : "=r"((r)[0]), "=r"((r)[1]), "=r"((r)[2]), "=r"((r)[3]) \
                 : "r"(addr))

#define MMA16816(c, a, b0, b1) \
    asm volatile("mma.sync.aligned.m16n8k16.row.col.f32.bf16.bf16.f32 " \
                 "{%0,%1,%2,%3}, {%4,%5,%6,%7}, {%8,%9}, {%0,%1,%2,%3};" \
                 : "+f"((c)[0]), "+f"((c)[1]), "+f"((c)[2]), "+f"((c)[3]) \
                 : "r"((a)[0]), "r"((a)[1]), "r"((a)[2]), "r"((a)[3]), \
                   "r"(b0), "r"(b1))

// Dummy: shifts the ncu capture window (capture lands on launch index 3)
// so corr_all gets profiled instead of offset_all.
__global__ void dummy_kernel() { g_dummy[threadIdx.x] = 0.f; }

// ---------------------------------------------------------------------------
// transpose_all: NCHW -> NHWC for all levels; folds the x[0] passthrough copy.
// ---------------------------------------------------------------------------
template<int S>
__device__ __forceinline__ void transpose_one(
    int local, const float* __restrict__ x, float* __restrict__ xtb,
    float* __restrict__ outb, float (*t)[33]) {
    constexpr int P = S * S;
    int tb = local & 3;
    int ct = (local >> 2) & 7;
    int pt = local >> 5;
    int p0 = pt * 32, c0 = ct * 32;
    const float* src = x + (size_t)tb * (256 * P);
    float* dst = xtb + (size_t)tb * (256 * P);
    int tx = threadIdx.x;
    bool copy = (tb < 2);
    float* cp = outb + (size_t)tb * (256 * P);
    for (int j = threadIdx.y; j < 32; j += 8) {
        float v = src[(c0 + j) * P + (p0 + tx)];
        t[j][tx] = v;
        if (copy) cp[(c0 + j) * P + (p0 + tx)] = v;
    }
    __syncthreads();
    for (int j = threadIdx.y; j < 32; j += 8)
        dst[(size_t)(p0 + j) * 256 + (c0 + tx)] = t[tx][j];
}

__global__ void transpose_all(const float* __restrict__ x0, const float* __restrict__ x1,
                              const float* __restrict__ x2, const float* __restrict__ x3,
                              float* __restrict__ out) {
    __shared__ float t[32][33];
    int id = blockIdx.x;
    if (id < 4096)      transpose_one<64>(id,        x0, g_xt,           out,           t);
    else if (id < 5120) transpose_one<32>(id - 4096, x1, g_xt + 4194304, out + 4194304, t);
    else if (id < 5376) transpose_one<16>(id - 5120, x2, g_xt + 5242880, out + 5242880, t);
    else                transpose_one< 8>(id - 5376, x3, g_xt + 5505024, out + 5505024, t);
}

// ---------------------------------------------------------------------------
// Weight prep: w_adapt[o][C][ky][kx] -> bf16 hi/lo in [l][o][K], K = k*256+C.
// ---------------------------------------------------------------------------
__global__ void wprep_kernel(const float* __restrict__ w0, const float* __restrict__ w1,
                             const float* __restrict__ w2, const float* __restrict__ w3) {
    int l = blockIdx.y;
    const float* src = (l == 0) ? w0 : (l == 1) ? w1 : (l == 2) ? w2 : w3;
    int idx = blockIdx.x * 256 + threadIdx.x;     // [0, 294912)
    int o = idx / 1152, j = idx - o * 1152;
    int K0 = 2 * j, K1 = K0 + 1;
    int k0 = K0 >> 8, C0 = K0 & 255;
    int k1 = K1 >> 8, C1 = K1 & 255;
    float a = src[o * 2304 + C0 * 9 + k0];
    float b = src[o * 2304 + C1 * 9 + k1];
    __nv_bfloat16 ah = __float2bfloat16_rn(a);
    __nv_bfloat16 bh = __float2bfloat16_rn(b);
    __nv_bfloat16 al = __float2bfloat16_rn(a - __bfloat162float(ah));
    __nv_bfloat16 bl = __float2bfloat16_rn(b - __bfloat162float(bh));
    size_t d = (size_t)l * 294912 + idx;
    g_wh[d] = ((unsigned)__bfloat16_as_ushort(bh) << 16) | __bfloat16_as_ushort(ah);
    g_wl[d] = ((unsigned)__bfloat16_as_ushort(bl) << 16) | __bfloat16_as_ushort(al);
}

// ---------------------------------------------------------------------------
// corr_all: warp per flat (level, b, pix).
// ---------------------------------------------------------------------------
template<int S, int D, int ST, int PD, int K2, int SP>
__device__ __forceinline__ void corr_one(int wloc, int lane,
                                         const float* __restrict__ xtb,
                                         float* __restrict__ corrb) {
    constexpr int P = S * S;
    int b = wloc / P, pix = wloc - b * P;
    int h = pix / S, w = pix - h * S;

    const float4* f1 = reinterpret_cast<const float4*>(
        xtb + ((size_t)(2 + b) * P + pix) * 256 + lane * 8);
    float4 u0 = f1[0], u1 = f1[1];
    const float* f2b = xtb + (size_t)b * P * 256;
    float* cw = corrb + (size_t)wloc * SP;

    int s = 0;
    for (int iy = 0; iy < D; iy++) {
        int py = h - PD + iy * ST;
        for (int ix = 0; ix < D; ix++, s++) {
            int px = w - PD + ix * ST;
            float v = 0.f;
            if ((unsigned)py < (unsigned)S && (unsigned)px < (unsigned)S) {
                const float4* f2 = reinterpret_cast<const float4*>(
                    f2b + ((size_t)py * S + px) * 256 + lane * 8);
                float4 q0 = f2[0], q1 = f2[1];
                v = u0.x * q0.x + u0.y * q0.y + u0.z * q0.z + u0.w * q0.w +
                    u1.x * q1.x + u1.y * q1.y + u1.z * q1.z + u1.w * q1.w;
            }
            v += __shfl_xor_sync(0xffffffffu, v, 16);
            v += __shfl_xor_sync(0xffffffffu, v, 8);
            v += __shfl_xor_sync(0xffffffffu, v, 4);
            v += __shfl_xor_sync(0xffffffffu, v, 2);
            v += __shfl_xor_sync(0xffffffffu, v, 1);
            if (lane == 0) cw[s] = v * (1.f / 256.f);
        }
    }
    for (int z = K2 + lane; z < SP; z += 32) cw[z] = 0.f;
}

__global__ void corr_all() {
    int w = (blockIdx.x * blockDim.x + threadIdx.x) >> 5;
    int lane = threadIdx.x & 31;
    if (w < 8192)       corr_one<64, 17, 2, 16, 289, 320>(w,         lane, g_xt,           g_corr);
    else if (w < 10240) corr_one<32, 17, 1,  8, 289, 320>(w - 8192,  lane, g_xt + 4194304, g_corr + 2621440);
    else if (w < 10752) corr_one<16,  9, 1,  4,  81,  96>(w - 10240, lane, g_xt + 5242880, g_corr + 3276800);
    else                corr_one< 8,  5, 1,  2,  25,  32>(w - 10752, lane, g_xt + 5505024, g_corr + 3325952);
}

// ---------------------------------------------------------------------------
// offset_all: block = 64 flat pixels x 72 outputs, 288 threads, 170 blocks.
// Shared arrays hoisted so all template instantiations share ONE allocation.
// ---------------------------------------------------------------------------
template<int K2, int SP>
__device__ __forceinline__ void offset_one(const float* __restrict__ w_off,
                                           const float* __restrict__ corrb,
                                           int local, int flatpb,
                                           float (*Ws)[73], float (*Cs)[65]) {
    int tid = threadIdx.x;
    int og = tid >> 4, pg = tid & 15;
    int pb = local * 64;

    float acc[4][4];
#pragma unroll
    for (int j = 0; j < 4; j++)
#pragma unroll
        for (int i = 0; i < 4; i++) acc[j][i] = 0.f;

    int wo = tid >> 2;
    int ws0 = (tid & 3) * 8;

    for (int cs = 0; cs < SP; cs += 32) {
#pragma unroll
        for (int u = 0; u < 8; u++) {
            int s = ws0 + u;
            int gs = cs + s;
            Ws[s][wo] = (gs < K2) ? w_off[(size_t)wo * K2 + gs] : 0.f;
        }
        for (int idx = tid; idx < 512; idx += 288) {
            int px = idx & 63, s4 = idx >> 6;
            float4 v = *reinterpret_cast<const float4*>(
                corrb + (size_t)(pb + px) * SP + cs + s4 * 4);
            Cs[s4 * 4 + 0][px] = v.x;
            Cs[s4 * 4 + 1][px] = v.y;
            Cs[s4 * 4 + 2][px] = v.z;
            Cs[s4 * 4 + 3][px] = v.w;
        }
        __syncthreads();
#pragma unroll 4
        for (int s = 0; s < 32; s++) {
            float c0 = Cs[s][pg];
            float c1 = Cs[s][pg + 16];
            float c2 = Cs[s][pg + 32];
            float c3 = Cs[s][pg + 48];
#pragma unroll
            for (int j = 0; j < 4; j++) {
                float wv = Ws[s][og * 4 + j];
                acc[j][0] = fmaf(wv, c0, acc[j][0]);
                acc[j][1] = fmaf(wv, c1, acc[j][1]);
                acc[j][2] = fmaf(wv, c2, acc[j][2]);
                acc[j][3] = fmaf(wv, c3, acc[j][3]);
            }
        }
        __syncthreads();
    }
#pragma unroll
    for (int i = 0; i < 4; i++)
#pragma unroll
        for (int j = 0; j < 4; j++)
            g_off[(size_t)(flatpb + pg + 16 * i) * 72 + og * 4 + j] = acc[j][i];
}

__global__ void __launch_bounds__(288) offset_all(
    const float* __restrict__ wo0, const float* __restrict__ wo1,
    const float* __restrict__ wo2, const float* __restrict__ wo3) {
    __shared__ float Ws[32][73];
    __shared__ float Cs[32][65];
    int id = blockIdx.x;
    if (id < 128)      offset_one<289, 320>(wo0, g_corr,           id,       id * 64,                 Ws, Cs);
    else if (id < 160) offset_one<289, 320>(wo1, g_corr + 2621440, id - 128, 8192  + (id - 128) * 64, Ws, Cs);
    else if (id < 168) offset_one< 81,  96>(wo2, g_corr + 3276800, id - 160, 10240 + (id - 160) * 64, Ws, Cs);
    else               offset_one< 25,  32>(wo3, g_corr + 3325952, id - 168, 10752 + (id - 168) * 64, Ws, Cs);
}

// ---------------------------------------------------------------------------
// im2col_all: warp per flat pixel; g_off/g_col indexed by flat id directly.
// ---------------------------------------------------------------------------
template<int S>
__device__ __forceinline__ void im2col_one(int wflat, int wloc, int lane,
                                           const float* __restrict__ xtb) {
    constexpr int P = S * S;
    int b = wloc / P, pix = wloc - b * P;
    int h = pix / S, w = pix - h * S;

    const float* op = g_off + (size_t)wflat * 72;
    const float* xi = xtb + (size_t)(2 + b) * P * 256;
    size_t rowb = (size_t)wflat * 1152;

    for (int q = 0; q < 36; q++) {
        int g = q / 9, k = q - g * 9;
        int ky = k / 3, kx = k - ky * 3;
        float fy = (float)(h + ky - 1) + op[q * 2];
        float fx = (float)(w + kx - 1) + op[q * 2 + 1];
        float fy0 = floorf(fy), fx0 = floorf(fx);
        float wy = fy - fy0, wx = fx - fx0;
        int y0 = (int)fy0, x0 = (int)fx0;
        float w00 = (1.f - wy) * (1.f - wx);
        float w01 = (1.f - wy) * wx;
        float w10 = wy * (1.f - wx);
        float w11 = wy * wx;
        bool vy0 = (unsigned)y0 < (unsigned)S, vy1 = (unsigned)(y0 + 1) < (unsigned)S;
        bool vx0 = (unsigned)x0 < (unsigned)S, vx1 = (unsigned)(x0 + 1) < (unsigned)S;
        bool v00 = vy0 && vx0, v01 = vy0 && vx1, v10 = vy1 && vx0, v11 = vy1 && vx1;

        const float* xc = xi + g * 64 + lane * 2;
        int i00 = (y0 * S + x0) * 256;
        float a0 = 0.f, a1 = 0.f;
        if (v00) { float2 u = *(const float2*)(xc + i00);
                   a0 += w00 * u.x; a1 += w00 * u.y; }
        if (v01) { float2 u = *(const float2*)(xc + i00 + 256);
                   a0 += w01 * u.x; a1 += w01 * u.y; }
        if (v10) { float2 u = *(const float2*)(xc + i00 + S * 256);
                   a0 += w10 * u.x; a1 += w10 * u.y; }
        if (v11) { float2 u = *(const float2*)(xc + i00 + S * 256 + 256);
                   a0 += w11 * u.x; a1 += w11 * u.y; }

        __nv_bfloat16 h0 = __float2bfloat16_rn(a0);
        __nv_bfloat16 h1 = __float2bfloat16_rn(a1);
        __nv_bfloat16 l0 = __float2bfloat16_rn(a0 - __bfloat162float(h0));
        __nv_bfloat16 l1 = __float2bfloat16_rn(a1 - __bfloat162float(h1));
        size_t d = rowb + k * 128 + g * 32 + lane;
        g_colh[d] = ((unsigned)__bfloat16_as_ushort(h1) << 16) | __bfloat16_as_ushort(h0);
        g_coll[d] = ((unsigned)__bfloat16_as_ushort(l1) << 16) | __bfloat16_as_ushort(l0);
    }
}

__global__ void im2col_all() {
    int w = (blockIdx.x * blockDim.x + threadIdx.x) >> 5;
    int lane = threadIdx.x & 31;
    if (w < 8192)       im2col_one<64>(w, w,         lane, g_xt);
    else if (w < 10240) im2col_one<32>(w, w - 8192,  lane, g_xt + 4194304);
    else if (w < 10752) im2col_one<16>(w, w - 10240, lane, g_xt + 5242880);
    else                im2col_one< 8>(w, w - 10752, lane, g_xt + 5505024);
}

// ---------------------------------------------------------------------------
// mma.sync bf16 GEMM, 3-term split, 128(M) x 128(N) CTA tiles. 8 warps of
// 32(M) x 64(N). K-chunks of 64 bf16, double-buffered cp.async, rows padded
// to 72 bf16 (144B). Stage: A 2x18432 + B 2x18432 = 73728B; x2 = 147456B.
// grid (85, 2), block 256.
// ---------------------------------------------------------------------------
#define ST_SIZE 73728
#define OFF_AH  0
#define OFF_AL  18432
#define OFF_BH  36864
#define OFF_BL  55296
#define GEMM_SMEM 147456

__global__ void __launch_bounds__(256) gemm_mma(float* __restrict__ out) {
    extern __shared__ __align__(128) char smem[];
    uint32_t sb = smem_u32(smem);
    int tid = threadIdx.x;
    int lane = tid & 31, warp = tid >> 5;
    int warp_m = warp & 3, warp_n = warp >> 2;   // 4 x 2 warps: 32M x 64N each

    int t = blockIdx.x, m0 = blockIdx.y * 128;
    int L, f, HW, lg, OB, PBL;
    if (t < 64)      { L = 0; f = t * 128;        HW = 4096; lg = 12; OB = 0;       PBL = 0;     }
    else if (t < 80) { L = 1; f = (t - 64) * 128; HW = 1024; lg = 10; OB = 4194304; PBL = 8192;  }
    else if (t < 84) { L = 2; f = (t - 80) * 128; HW = 256;  lg = 8;  OB = 5242880; PBL = 10240; }
    else             { L = 3; f = 0;              HW = 64;   lg = 6;  OB = 5505024; PBL = 10752; }
    int p0 = PBL + f;

    const unsigned* GAh = g_wh + (size_t)(L * 256 + m0) * 1152;
    const unsigned* GAl = g_wl + (size_t)(L * 256 + m0) * 1152;
    const unsigned* GBh = g_colh + (size_t)p0 * 1152;
    const unsigned* GBl = g_coll + (size_t)p0 * 1152;

    auto stage = [&](int ci, int buf) {
        uint32_t base = sb + buf * ST_SIZE;
        int kc = ci * 32;
#pragma unroll
        for (int i = 0; i < 4; i++) {
            int u = i * 256 + tid;              // [0,1024): r=0..127, c=0..7
            int r = u >> 3, c = u & 7;
            uint32_t so = (uint32_t)(r * 144 + c * 16);
            CPA16(base + OFF_AH + so, GAh + (size_t)r * 1152 + kc + c * 4);
            CPA16(base + OFF_AL + so, GAl + (size_t)r * 1152 + kc + c * 4);
            CPA16(base + OFF_BH + so, GBh + (size_t)r * 1152 + kc + c * 4);
            CPA16(base + OFF_BL + so, GBl + (size_t)r * 1152 + kc + c * 4);
        }
    };

    float acc[2][8][4];
#pragma unroll
    for (int am = 0; am < 2; am++)
#pragma unroll
        for (int an = 0; an < 8; an++)
#pragma unroll
            for (int i = 0; i < 4; i++) acc[am][an][i] = 0.f;

    uint32_t a_row = (uint32_t)(warp_m * 32 + (lane & 15));
    uint32_t a_koff = (uint32_t)((lane >> 4) * 16);
    uint32_t b_row = (uint32_t)(warp_n * 64 + (lane & 7) + ((lane >> 4) << 3));
    uint32_t b_koff = (uint32_t)(((lane >> 3) & 1) * 16);

    stage(0, 0);
    CPA_COMMIT();

    for (int ci = 0; ci < 36; ci++) {
        if (ci + 1 < 36) {
            stage(ci + 1, (ci + 1) & 1);
            CPA_COMMIT();
            CPA_WAIT1();
        } else {
            CPA_WAIT0();
        }
        __syncthreads();
        uint32_t base = sb + (ci & 1) * ST_SIZE;
#pragma unroll
        for (int ks = 0; ks < 4; ks++) {
            uint32_t ao = a_row * 144 + (uint32_t)(ks * 32) + a_koff;
            uint32_t bo = b_row * 144 + (uint32_t)(ks * 32) + b_koff;
            uint32_t ah0[4], ah1[4], al0[4], al1[4];
            uint32_t bh[4][4], bl[4][4];
            LDSM4(ah0, base + OFF_AH + ao);
            LDSM4(ah1, base + OFF_AH + ao + 16 * 144);
            LDSM4(al0, base + OFF_AL + ao);
            LDSM4(al1, base + OFF_AL + ao + 16 * 144);
#pragma unroll
            for (int j = 0; j < 4; j++) {
                LDSM4(bh[j], base + OFF_BH + bo + j * (16 * 144));
                LDSM4(bl[j], base + OFF_BL + bo + j * (16 * 144));
            }
            // hh
#pragma unroll
            for (int j = 0; j < 4; j++) {
                MMA16816(acc[0][2 * j],     ah0, bh[j][0], bh[j][1]);
                MMA16816(acc[0][2 * j + 1], ah0, bh[j][2], bh[j][3]);
                MMA16816(acc[1][2 * j],     ah1, bh[j][0], bh[j][1]);
                MMA16816(acc[1][2 * j + 1], ah1, bh[j][2], bh[j][3]);
            }
            // hl
#pragma unroll
            for (int j = 0; j < 4; j++) {
                MMA16816(acc[0][2 * j],     ah0, bl[j][0], bl[j][1]);
                MMA16816(acc[0][2 * j + 1], ah0, bl[j][2], bl[j][3]);
                MMA16816(acc[1][2 * j],     ah1, bl[j][0], bl[j][1]);
                MMA16816(acc[1][2 * j + 1], ah1, bl[j][2], bl[j][3]);
            }
            // lh
#pragma unroll
            for (int j = 0; j < 4; j++) {
                MMA16816(acc[0][2 * j],     al0, bh[j][0], bh[j][1]);
                MMA16816(acc[0][2 * j + 1], al0, bh[j][2], bh[j][3]);
                MMA16816(acc[1][2 * j],     al1, bh[j][0], bh[j][1]);
                MMA16816(acc[1][2 * j + 1], al1, bh[j][2], bh[j][3]);
            }
        }
        __syncthreads();
    }

    // Epilogue: ReLU + store. b/pix recomputed per column (L3 tile spans
    // both images). fc even -> float2 stays within one image row.
    float* Obase = out + OB;
#pragma unroll
    for (int am = 0; am < 2; am++) {
        int o = m0 + warp_m * 32 + am * 16 + (lane >> 2);
#pragma unroll
        for (int an = 0; an < 8; an++) {
            int c = warp_n * 64 + an * 8 + (lane & 3) * 2;
            int fc = f + c;
            int bb = fc >> lg;
            int pixc = fc - (bb << lg);
            float* Op = Obase + ((size_t)(2 + bb) * 256) * HW + pixc;
            float2 v0 = make_float2(fmaxf(acc[am][an][0], 0.f),
                                    fmaxf(acc[am][an][1], 0.f));
            float2 v1 = make_float2(fmaxf(acc[am][an][2], 0.f),
                                    fmaxf(acc[am][an][3], 0.f));
            *reinterpret_cast<float2*>(Op + (size_t)o * HW) = v0;
            *reinterpret_cast<float2*>(Op + (size_t)(o + 8) * HW) = v1;
        }
    }
}

extern "C" void kernel_launch(void* const* d_in, const int* in_sizes, int n_in,
                              void* d_out, int out_size) {
    // Runtime input classification by element count (metadata interleaves
    // w_off{i}/w_adapt{i} — do NOT trust signature order).
    const float* xs[4]   = {0, 0, 0, 0};
    const float* wofs[4] = {0, 0, 0, 0};
    const float* wads[4] = {0, 0, 0, 0};
    int n_adapt = 0, n_off_big = 0;
    for (int i = 0; i < n_in; i++) {
        const float* p = (const float*)d_in[i];
        switch (in_sizes[i]) {
            case 4194304: xs[0] = p; break;
            case 1048576: xs[1] = p; break;
            case 262144:  xs[2] = p; break;
            case 65536:   xs[3] = p; break;
            case 589824:  wads[n_adapt++] = p; break;
            case 20808:   wofs[n_off_big++] = p; break;
            case 5832:    wofs[2] = p; break;
            case 1800:    wofs[3] = p; break;
            default: break;
        }
    }
    float* out = (float*)d_out;

    cudaFuncSetAttribute(gemm_mma, cudaFuncAttributeMaxDynamicSharedMemorySize,
                         GEMM_SMEM);

    dummy_kernel<<<1, 32>>>();
    wprep_kernel<<<dim3(1152, 4), 256>>>(wads[0], wads[1], wads[2], wads[3]);
    transpose_all<<<5440, dim3(32, 8)>>>(xs[0], xs[1], xs[2], xs[3], out);
    corr_all<<<1360, 256>>>();
    offset_all<<<170, 288>>>(wofs[0], wofs[1], wofs[2], wofs[3]);
    im2col_all<<<1360, 256>>>();
    gemm_mma<<<dim3(85, 2), 256, GEMM_SMEM>>>(out);
}

// round 14
// speedup vs baseline: 1.1644x; 1.1644x over previous
#include <cuda_runtime.h>
#include <cuda_bf16.h>
#include <cstdint>
#include <math.h>

// ---------------------------------------------------------------------------
// CorrelationAdaptor, fully batched: 7 launches.
//   wprep -> transpose_all(+copy) -> xb_convert -> corr_all(bf16,4px/warp)
//   -> offset_all -> im2col_all -> gemm_mma (mma.sync bf16 3-term, 128x64)
// Levels: S={64,32,16,8}, disp={8,8,4,2}, stride={2,1,1,1}
// K2={289,289,81,25}, pad={16,8,4,2}, SP={320,320,96,32}
// Flat pixel space: bases {0, 8192, 10240, 10752}, total 10880.
// g_xt bases {0,4194304,5242880,5505024}; g_xb = /2; g_corr bases
// {0,2621440,3276800,3325952}; out bases {0,4194304,5242880,5505024}.
// NOTE: harness compiles .target sm_100 (no 'a') -> tcgen05 unavailable.
// ---------------------------------------------------------------------------

__device__ float g_xt  [5570560];                        // NHWC x fp32
__device__ __align__(16) unsigned g_xb[2785280];         // NHWC x bf16x2
__device__ float g_corr[3330048];                        // [flat bp][SP]
__device__ float g_off [10880 * 72];                     // [flat p][72]
__device__ __align__(16) unsigned g_colh[10880 * 1152];  // bf16x2 col hi [p][K/2]
__device__ __align__(16) unsigned g_coll[10880 * 1152];  // bf16x2 col lo
__device__ __align__(16) unsigned g_wh  [4 * 256 * 1152];// bf16x2 W hi [l][o][K/2]
__device__ __align__(16) unsigned g_wl  [4 * 256 * 1152];// bf16x2 W lo

__device__ __forceinline__ uint32_t smem_u32(const void* p) {
    uint32_t a;
    asm("{ .reg .u64 t; cvta.to.shared.u64 t, %1; cvt.u32.u64 %0, t; }"
        : "=r"(a) : "l"(p));
    return a;
}
__device__ __forceinline__ float bf_lo(unsigned u) {
    return __uint_as_float(u << 16);
}
__device__ __forceinline__ float bf_hi(unsigned u) {
    return __uint_as_float(u & 0xffff0000u);
}

#define CPA16(dst, src) \
    asm volatile("cp.async.cg.shared.global [%0], [%1], 16;" \
                 :: "r"(dst), "l"(src))
#define CPA_COMMIT() asm volatile("cp.async.commit_group;" ::: "memory")
#define CPA_WAIT1()  asm volatile("cp.async.wait_group 1;" ::: "memory")
#define CPA_WAIT0()  asm volatile("cp.async.wait_group 0;" ::: "memory")

#define LDSM4(r, addr) \
    asm volatile("ldmatrix.sync.aligned.m8n8.x4.shared.b16 {%0,%1,%2,%3}, [%4];" \
                 : "=r"((r)[0]), "=r"((r)[1]), "=r"((r)[2]), "=r"((r)[3]) \
                 : "r"(addr))

#define MMA16816(c, a, b0, b1) \
    asm volatile("mma.sync.aligned.m16n8k16.row.col.f32.bf16.bf16.f32 " \
                 "{%0,%1,%2,%3}, {%4,%5,%6,%7}, {%8,%9}, {%0,%1,%2,%3};" \
                 : "+f"((c)[0]), "+f"((c)[1]), "+f"((c)[2]), "+f"((c)[3]) \
                 : "r"((a)[0]), "r"((a)[1]), "r"((a)[2]), "r"((a)[3]), \
                   "r"(b0), "r"(b1))

// ---------------------------------------------------------------------------
// transpose_all: NCHW -> NHWC fp32 for all levels + x[0] passthrough copy.
// ---------------------------------------------------------------------------
template<int S>
__device__ __forceinline__ void transpose_one(
    int local, const float* __restrict__ x, float* __restrict__ xtb,
    float* __restrict__ outb, float (*t)[33]) {
    constexpr int P = S * S;
    int tb = local & 3;
    int ct = (local >> 2) & 7;
    int pt = local >> 5;
    int p0 = pt * 32, c0 = ct * 32;
    const float* src = x + (size_t)tb * (256 * P);
    float* dst = xtb + (size_t)tb * (256 * P);
    int tx = threadIdx.x;
    bool copy = (tb < 2);
    float* cp = outb + (size_t)tb * (256 * P);
    for (int j = threadIdx.y; j < 32; j += 8) {
        float v = src[(c0 + j) * P + (p0 + tx)];
        t[j][tx] = v;
        if (copy) cp[(c0 + j) * P + (p0 + tx)] = v;
    }
    __syncthreads();
    for (int j = threadIdx.y; j < 32; j += 8)
        dst[(size_t)(p0 + j) * 256 + (c0 + tx)] = t[tx][j];
}

__global__ void transpose_all(const float* __restrict__ x0, const float* __restrict__ x1,
                              const float* __restrict__ x2, const float* __restrict__ x3,
                              float* __restrict__ out) {
    __shared__ float t[32][33];
    int id = blockIdx.x;
    if (id < 4096)      transpose_one<64>(id,        x0, g_xt,           out,           t);
    else if (id < 5120) transpose_one<32>(id - 4096, x1, g_xt + 4194304, out + 4194304, t);
    else if (id < 5376) transpose_one<16>(id - 5120, x2, g_xt + 5242880, out + 5242880, t);
    else                transpose_one< 8>(id - 5376, x3, g_xt + 5505024, out + 5505024, t);
}

// ---------------------------------------------------------------------------
// xb_convert: g_xt fp32 -> g_xb bf16x2 (channel pairs). 10880 x 256 threads.
// ---------------------------------------------------------------------------
__global__ void xb_convert() {
    int i = blockIdx.x * 256 + threadIdx.x;   // [0, 2785280)
    float2 v = *reinterpret_cast<const float2*>(g_xt + 2 * (size_t)i);
    __nv_bfloat16 a = __float2bfloat16_rn(v.x);
    __nv_bfloat16 b = __float2bfloat16_rn(v.y);
    g_xb[i] = ((unsigned)__bfloat16_as_ushort(b) << 16) | __bfloat16_as_ushort(a);
}

// ---------------------------------------------------------------------------
// Weight prep: w_adapt[o][C][ky][kx] -> bf16 hi/lo in [l][o][K], K = k*256+C.
// ---------------------------------------------------------------------------
__global__ void wprep_kernel(const float* __restrict__ w0, const float* __restrict__ w1,
                             const float* __restrict__ w2, const float* __restrict__ w3) {
    int l = blockIdx.y;
    const float* src = (l == 0) ? w0 : (l == 1) ? w1 : (l == 2) ? w2 : w3;
    int idx = blockIdx.x * 256 + threadIdx.x;     // [0, 294912)
    int o = idx / 1152, j = idx - o * 1152;
    int K0 = 2 * j, K1 = K0 + 1;
    int k0 = K0 >> 8, C0 = K0 & 255;
    int k1 = K1 >> 8, C1 = K1 & 255;
    float a = src[o * 2304 + C0 * 9 + k0];
    float b = src[o * 2304 + C1 * 9 + k1];
    __nv_bfloat16 ah = __float2bfloat16_rn(a);
    __nv_bfloat16 bh = __float2bfloat16_rn(b);
    __nv_bfloat16 al = __float2bfloat16_rn(a - __bfloat162float(ah));
    __nv_bfloat16 bl = __float2bfloat16_rn(b - __bfloat162float(bh));
    size_t d = (size_t)l * 294912 + idx;
    g_wh[d] = ((unsigned)__bfloat16_as_ushort(bh) << 16) | __bfloat16_as_ushort(ah);
    g_wl[d] = ((unsigned)__bfloat16_as_ushort(bl) << 16) | __bfloat16_as_ushort(al);
}

// ---------------------------------------------------------------------------
// corr_all v2: warp handles 4 consecutive flat pixels; 8 lanes per pixel,
// each lane 32 channels (bf16, 64B). Per shift: 4 LDG.128 + 32 FFMA +
// 3 SHFL (shared by 4 pixels). corr = dot/256, 0 out of bounds.
// grid 340 x 256.
// ---------------------------------------------------------------------------
template<int S, int D, int ST, int PD, int K2, int SP>
__device__ __forceinline__ void corr4(int locbase, int lane,
                                      const unsigned* __restrict__ xbB,
                                      float* __restrict__ corrb) {
    constexpr int P = S * S;
    int p = lane >> 3, cl = lane & 7;
    int wloc = locbase + p;
    int b = wloc / P, pix = wloc - b * P;
    int h = pix / S, w = pix - h * S;

    const uint4* f1p = reinterpret_cast<const uint4*>(
        xbB + ((size_t)(2 + b) * P + pix) * 128 + cl * 16);
    uint4 a0 = f1p[0], a1 = f1p[1], a2 = f1p[2], a3 = f1p[3];
    unsigned pk[16] = {a0.x, a0.y, a0.z, a0.w, a1.x, a1.y, a1.z, a1.w,
                       a2.x, a2.y, a2.z, a2.w, a3.x, a3.y, a3.z, a3.w};
    float f1v[32];
#pragma unroll
    for (int i = 0; i < 16; i++) {
        f1v[2 * i]     = bf_lo(pk[i]);
        f1v[2 * i + 1] = bf_hi(pk[i]);
    }

    const unsigned* f2base = xbB + (size_t)b * P * 128;
    float* cw = corrb + (size_t)wloc * SP;

    int s = 0;
    for (int iy = 0; iy < D; iy++) {
        int py = h - PD + iy * ST;
        for (int ix = 0; ix < D; ix++, s++) {
            int px = w - PD + ix * ST;
            float acc0 = 0.f, acc1 = 0.f;
            if ((unsigned)py < (unsigned)S && (unsigned)px < (unsigned)S) {
                const uint4* f2p = reinterpret_cast<const uint4*>(
                    f2base + ((size_t)py * S + px) * 128 + cl * 16);
                uint4 q0 = f2p[0], q1 = f2p[1], q2 = f2p[2], q3 = f2p[3];
                unsigned qk[16] = {q0.x, q0.y, q0.z, q0.w, q1.x, q1.y, q1.z, q1.w,
                                   q2.x, q2.y, q2.z, q2.w, q3.x, q3.y, q3.z, q3.w};
#pragma unroll
                for (int i = 0; i < 16; i += 2) {
                    acc0 = fmaf(f1v[2 * i],     bf_lo(qk[i]),     acc0);
                    acc0 = fmaf(f1v[2 * i + 1], bf_hi(qk[i]),     acc0);
                    acc1 = fmaf(f1v[2 * i + 2], bf_lo(qk[i + 1]), acc1);
                    acc1 = fmaf(f1v[2 * i + 3], bf_hi(qk[i + 1]), acc1);
                }
            }
            float v = acc0 + acc1;
            v += __shfl_xor_sync(0xffffffffu, v, 4);
            v += __shfl_xor_sync(0xffffffffu, v, 2);
            v += __shfl_xor_sync(0xffffffffu, v, 1);
            if (cl == 0) cw[s] = v * (1.f / 256.f);
        }
    }
    for (int z = K2 + cl; z < SP; z += 8) cw[z] = 0.f;
}

__global__ void __launch_bounds__(256) corr_all() {
    int gw = (blockIdx.x * blockDim.x + threadIdx.x) >> 5;   // [0, 2720)
    int lane = threadIdx.x & 31;
    if (gw < 2048)      corr4<64, 17, 2, 16, 289, 320>(gw * 4,          lane, g_xb,           g_corr);
    else if (gw < 2560) corr4<32, 17, 1,  8, 289, 320>((gw - 2048) * 4, lane, g_xb + 2097152, g_corr + 2621440);
    else if (gw < 2688) corr4<16,  9, 1,  4,  81,  96>((gw - 2560) * 4, lane, g_xb + 2621440, g_corr + 3276800);
    else                corr4< 8,  5, 1,  2,  25,  32>((gw - 2688) * 4, lane, g_xb + 2752512, g_corr + 3325952);
}

// ---------------------------------------------------------------------------
// offset_all: block = 64 flat pixels x 72 outputs, 288 threads, 170 blocks.
// ---------------------------------------------------------------------------
template<int K2, int SP>
__device__ __forceinline__ void offset_one(const float* __restrict__ w_off,
                                           const float* __restrict__ corrb,
                                           int local, int flatpb,
                                           float (*Ws)[73], float (*Cs)[65]) {
    int tid = threadIdx.x;
    int og = tid >> 4, pg = tid & 15;
    int pb = local * 64;

    float acc[4][4];
#pragma unroll
    for (int j = 0; j < 4; j++)
#pragma unroll
        for (int i = 0; i < 4; i++) acc[j][i] = 0.f;

    int wo = tid >> 2;
    int ws0 = (tid & 3) * 8;

    for (int cs = 0; cs < SP; cs += 32) {
#pragma unroll
        for (int u = 0; u < 8; u++) {
            int s = ws0 + u;
            int gs = cs + s;
            Ws[s][wo] = (gs < K2) ? w_off[(size_t)wo * K2 + gs] : 0.f;
        }
        for (int idx = tid; idx < 512; idx += 288) {
            int px = idx & 63, s4 = idx >> 6;
            float4 v = *reinterpret_cast<const float4*>(
                corrb + (size_t)(pb + px) * SP + cs + s4 * 4);
            Cs[s4 * 4 + 0][px] = v.x;
            Cs[s4 * 4 + 1][px] = v.y;
            Cs[s4 * 4 + 2][px] = v.z;
            Cs[s4 * 4 + 3][px] = v.w;
        }
        __syncthreads();
#pragma unroll 4
        for (int s = 0; s < 32; s++) {
            float c0 = Cs[s][pg];
            float c1 = Cs[s][pg + 16];
            float c2 = Cs[s][pg + 32];
            float c3 = Cs[s][pg + 48];
#pragma unroll
            for (int j = 0; j < 4; j++) {
                float wv = Ws[s][og * 4 + j];
                acc[j][0] = fmaf(wv, c0, acc[j][0]);
                acc[j][1] = fmaf(wv, c1, acc[j][1]);
                acc[j][2] = fmaf(wv, c2, acc[j][2]);
                acc[j][3] = fmaf(wv, c3, acc[j][3]);
            }
        }
        __syncthreads();
    }
#pragma unroll
    for (int i = 0; i < 4; i++)
#pragma unroll
        for (int j = 0; j < 4; j++)
            g_off[(size_t)(flatpb + pg + 16 * i) * 72 + og * 4 + j] = acc[j][i];
}

__global__ void __launch_bounds__(288) offset_all(
    const float* __restrict__ wo0, const float* __restrict__ wo1,
    const float* __restrict__ wo2, const float* __restrict__ wo3) {
    __shared__ float Ws[32][73];
    __shared__ float Cs[32][65];
    int id = blockIdx.x;
    if (id < 128)      offset_one<289, 320>(wo0, g_corr,           id,       id * 64,                 Ws, Cs);
    else if (id < 160) offset_one<289, 320>(wo1, g_corr + 2621440, id - 128, 8192  + (id - 128) * 64, Ws, Cs);
    else if (id < 168) offset_one< 81,  96>(wo2, g_corr + 3276800, id - 160, 10240 + (id - 160) * 64, Ws, Cs);
    else               offset_one< 25,  32>(wo3, g_corr + 3325952, id - 168, 10752 + (id - 168) * 64, Ws, Cs);
}

// ---------------------------------------------------------------------------
// im2col_all: warp per flat pixel; bilinear -> bf16 hi/lo [p][K], K=k*256+C.
// ---------------------------------------------------------------------------
template<int S>
__device__ __forceinline__ void im2col_one(int wflat, int wloc, int lane,
                                           const float* __restrict__ xtb) {
    constexpr int P = S * S;
    int b = wloc / P, pix = wloc - b * P;
    int h = pix / S, w = pix - h * S;

    const float* op = g_off + (size_t)wflat * 72;
    const float* xi = xtb + (size_t)(2 + b) * P * 256;
    size_t rowb = (size_t)wflat * 1152;

    for (int q = 0; q < 36; q++) {
        int g = q / 9, k = q - g * 9;
        int ky = k / 3, kx = k - ky * 3;
        float fy = (float)(h + ky - 1) + op[q * 2];
        float fx = (float)(w + kx - 1) + op[q * 2 + 1];
        float fy0 = floorf(fy), fx0 = floorf(fx);
        float wy = fy - fy0, wx = fx - fx0;
        int y0 = (int)fy0, x0 = (int)fx0;
        float w00 = (1.f - wy) * (1.f - wx);
        float w01 = (1.f - wy) * wx;
        float w10 = wy * (1.f - wx);
        float w11 = wy * wx;
        bool vy0 = (unsigned)y0 < (unsigned)S, vy1 = (unsigned)(y0 + 1) < (unsigned)S;
        bool vx0 = (unsigned)x0 < (unsigned)S, vx1 = (unsigned)(x0 + 1) < (unsigned)S;
        bool v00 = vy0 && vx0, v01 = vy0 && vx1, v10 = vy1 && vx0, v11 = vy1 && vx1;

        const float* xc = xi + g * 64 + lane * 2;
        int i00 = (y0 * S + x0) * 256;
        float a0 = 0.f, a1 = 0.f;
        if (v00) { float2 u = *(const float2*)(xc + i00);
                   a0 += w00 * u.x; a1 += w00 * u.y; }
        if (v01) { float2 u = *(const float2*)(xc + i00 + 256);
                   a0 += w01 * u.x; a1 += w01 * u.y; }
        if (v10) { float2 u = *(const float2*)(xc + i00 + S * 256);
                   a0 += w10 * u.x; a1 += w10 * u.y; }
        if (v11) { float2 u = *(const float2*)(xc + i00 + S * 256 + 256);
                   a0 += w11 * u.x; a1 += w11 * u.y; }

        __nv_bfloat16 h0 = __float2bfloat16_rn(a0);
        __nv_bfloat16 h1 = __float2bfloat16_rn(a1);
        __nv_bfloat16 l0 = __float2bfloat16_rn(a0 - __bfloat162float(h0));
        __nv_bfloat16 l1 = __float2bfloat16_rn(a1 - __bfloat162float(h1));
        size_t d = rowb + k * 128 + g * 32 + lane;
        g_colh[d] = ((unsigned)__bfloat16_as_ushort(h1) << 16) | __bfloat16_as_ushort(h0);
        g_coll[d] = ((unsigned)__bfloat16_as_ushort(l1) << 16) | __bfloat16_as_ushort(l0);
    }
}

__global__ void im2col_all() {
    int w = (blockIdx.x * blockDim.x + threadIdx.x) >> 5;
    int lane = threadIdx.x & 31;
    if (w < 8192)       im2col_one<64>(w, w,         lane, g_xt);
    else if (w < 10240) im2col_one<32>(w, w - 8192,  lane, g_xt + 4194304);
    else if (w < 10752) im2col_one<16>(w, w - 10240, lane, g_xt + 5242880);
    else                im2col_one< 8>(w, w - 10752, lane, g_xt + 5505024);
}

// ---------------------------------------------------------------------------
// mma.sync bf16 GEMM, 3-term split. 128(M) x 64(N) CTA, 8 warps (32x32).
// (REVERTED from 128x128 — that retile cost +40us: 147KB smem -> 1 CTA/SM.)
// grid (170, 2), block 256.
// ---------------------------------------------------------------------------
#define ST_SIZE 55296
#define OFF_AH  0
#define OFF_AL  18432
#define OFF_BH  36864
#define OFF_BL  46080
#define GEMM_SMEM 110592

__global__ void __launch_bounds__(256) gemm_mma(float* __restrict__ out) {
    extern __shared__ __align__(128) char smem[];
    uint32_t sb = smem_u32(smem);
    int tid = threadIdx.x;
    int lane = tid & 31, warp = tid >> 5;
    int warp_m = warp & 3, warp_n = warp >> 2;   // 4 x 2 warps

    int t = blockIdx.x, m0 = blockIdx.y * 128;
    int L, f, HW, OB, PBL;
    if (t < 128)      { L = 0; f = t * 64;         HW = 4096; OB = 0;       PBL = 0;     }
    else if (t < 160) { L = 1; f = (t - 128) * 64; HW = 1024; OB = 4194304; PBL = 8192;  }
    else if (t < 168) { L = 2; f = (t - 160) * 64; HW = 256;  OB = 5242880; PBL = 10240; }
    else              { L = 3; f = (t - 168) * 64; HW = 64;   OB = 5505024; PBL = 10752; }
    int p0 = PBL + f;
    int b = f / HW, pix = f - b * HW;

    const unsigned* GAh = g_wh + (size_t)(L * 256 + m0) * 1152;
    const unsigned* GAl = g_wl + (size_t)(L * 256 + m0) * 1152;
    const unsigned* GBh = g_colh + (size_t)p0 * 1152;
    const unsigned* GBl = g_coll + (size_t)p0 * 1152;

    auto stage = [&](int ci, int buf) {
        uint32_t base = sb + buf * ST_SIZE;
        int kc = ci * 32;
#pragma unroll
        for (int i = 0; i < 4; i++) {
            int u = i * 256 + tid;
            int r = u >> 3, c = u & 7;
            uint32_t so = (uint32_t)(r * 144 + c * 16);
            CPA16(base + OFF_AH + so, GAh + (size_t)r * 1152 + kc + c * 4);
            CPA16(base + OFF_AL + so, GAl + (size_t)r * 1152 + kc + c * 4);
        }
#pragma unroll
        for (int i = 0; i < 2; i++) {
            int u = i * 256 + tid;
            int r = u >> 3, c = u & 7;
            uint32_t so = (uint32_t)(r * 144 + c * 16);
            CPA16(base + OFF_BH + so, GBh + (size_t)r * 1152 + kc + c * 4);
            CPA16(base + OFF_BL + so, GBl + (size_t)r * 1152 + kc + c * 4);
        }
    };

    float acc[2][4][4];
#pragma unroll
    for (int am = 0; am < 2; am++)
#pragma unroll
        for (int an = 0; an < 4; an++)
#pragma unroll
            for (int i = 0; i < 4; i++) acc[am][an][i] = 0.f;

    uint32_t a_row = (uint32_t)(warp_m * 32 + (lane & 15));
    uint32_t a_koff = (uint32_t)((lane >> 4) * 16);
    uint32_t b_row = (uint32_t)(warp_n * 32 + (lane & 7) + ((lane >> 4) << 3));
    uint32_t b_koff = (uint32_t)(((lane >> 3) & 1) * 16);

    stage(0, 0);
    CPA_COMMIT();

    for (int ci = 0; ci < 36; ci++) {
        if (ci + 1 < 36) {
            stage(ci + 1, (ci + 1) & 1);
            CPA_COMMIT();
            CPA_WAIT1();
        } else {
            CPA_WAIT0();
        }
        __syncthreads();
        uint32_t base = sb + (ci & 1) * ST_SIZE;
#pragma unroll
        for (int ks = 0; ks < 4; ks++) {
            uint32_t ao = a_row * 144 + (uint32_t)(ks * 32) + a_koff;
            uint32_t bo = b_row * 144 + (uint32_t)(ks * 32) + b_koff;
            uint32_t ah0[4], ah1[4], al0[4], al1[4];
            uint32_t bh0[4], bh1[4], bl0[4], bl1[4];
            LDSM4(ah0, base + OFF_AH + ao);
            LDSM4(ah1, base + OFF_AH + ao + 16 * 144);
            LDSM4(al0, base + OFF_AL + ao);
            LDSM4(al1, base + OFF_AL + ao + 16 * 144);
            LDSM4(bh0, base + OFF_BH + bo);
            LDSM4(bh1, base + OFF_BH + bo + 16 * 144);
            LDSM4(bl0, base + OFF_BL + bo);
            LDSM4(bl1, base + OFF_BL + bo + 16 * 144);

            MMA16816(acc[0][0], ah0, bh0[0], bh0[1]);
            MMA16816(acc[0][1], ah0, bh0[2], bh0[3]);
            MMA16816(acc[0][2], ah0, bh1[0], bh1[1]);
            MMA16816(acc[0][3], ah0, bh1[2], bh1[3]);
            MMA16816(acc[1][0], ah1, bh0[0], bh0[1]);
            MMA16816(acc[1][1], ah1, bh0[2], bh0[3]);
            MMA16816(acc[1][2], ah1, bh1[0], bh1[1]);
            MMA16816(acc[1][3], ah1, bh1[2], bh1[3]);

            MMA16816(acc[0][0], ah0, bl0[0], bl0[1]);
            MMA16816(acc[0][1], ah0, bl0[2], bl0[3]);
            MMA16816(acc[0][2], ah0, bl1[0], bl1[1]);
            MMA16816(acc[0][3], ah0, bl1[2], bl1[3]);
            MMA16816(acc[1][0], ah1, bl0[0], bl0[1]);
            MMA16816(acc[1][1], ah1, bl0[2], bl0[3]);
            MMA16816(acc[1][2], ah1, bl1[0], bl1[1]);
            MMA16816(acc[1][3], ah1, bl1[2], bl1[3]);

            MMA16816(acc[0][0], al0, bh0[0], bh0[1]);
            MMA16816(acc[0][1], al0, bh0[2], bh0[3]);
            MMA16816(acc[0][2], al0, bh1[0], bh1[1]);
            MMA16816(acc[0][3], al0, bh1[2], bh1[3]);
            MMA16816(acc[1][0], al1, bh0[0], bh0[1]);
            MMA16816(acc[1][1], al1, bh0[2], bh0[3]);
            MMA16816(acc[1][2], al1, bh1[0], bh1[1]);
            MMA16816(acc[1][3], al1, bh1[2], bh1[3]);
        }
        __syncthreads();
    }

    float* Ob = out + OB + ((size_t)(2 + b) * 256) * HW + pix;
#pragma unroll
    for (int am = 0; am < 2; am++) {
        int o = m0 + warp_m * 32 + am * 16 + (lane >> 2);
#pragma unroll
        for (int an = 0; an < 4; an++) {
            int c = warp_n * 32 + an * 8 + (lane & 3) * 2;
            float2 v0 = make_float2(fmaxf(acc[am][an][0], 0.f),
                                    fmaxf(acc[am][an][1], 0.f));
            float2 v1 = make_float2(fmaxf(acc[am][an][2], 0.f),
                                    fmaxf(acc[am][an][3], 0.f));
            *reinterpret_cast<float2*>(Ob + (size_t)o * HW + c) = v0;
            *reinterpret_cast<float2*>(Ob + (size_t)(o + 8) * HW + c) = v1;
        }
    }
}

extern "C" void kernel_launch(void* const* d_in, const int* in_sizes, int n_in,
                              void* d_out, int out_size) {
    // Runtime input classification by element count (metadata interleaves
    // w_off{i}/w_adapt{i} — do NOT trust signature order).
    const float* xs[4]   = {0, 0, 0, 0};
    const float* wofs[4] = {0, 0, 0, 0};
    const float* wads[4] = {0, 0, 0, 0};
    int n_adapt = 0, n_off_big = 0;
    for (int i = 0; i < n_in; i++) {
        const float* p = (const float*)d_in[i];
        switch (in_sizes[i]) {
            case 4194304: xs[0] = p; break;
            case 1048576: xs[1] = p; break;
            case 262144:  xs[2] = p; break;
            case 65536:   xs[3] = p; break;
            case 589824:  wads[n_adapt++] = p; break;
            case 20808:   wofs[n_off_big++] = p; break;
            case 5832:    wofs[2] = p; break;
            case 1800:    wofs[3] = p; break;
            default: break;
        }
    }
    float* out = (float*)d_out;

    cudaFuncSetAttribute(gemm_mma, cudaFuncAttributeMaxDynamicSharedMemorySize,
                         GEMM_SMEM);

    wprep_kernel<<<dim3(1152, 4), 256>>>(wads[0], wads[1], wads[2], wads[3]);
    transpose_all<<<5440, dim3(32, 8)>>>(xs[0], xs[1], xs[2], xs[3], out);
    xb_convert<<<10880, 256>>>();
    corr_all<<<340, 256>>>();
    offset_all<<<170, 288>>>(wofs[0], wofs[1], wofs[2], wofs[3]);
    im2col_all<<<1360, 256>>>();
    gemm_mma<<<dim3(170, 2), 256, GEMM_SMEM>>>(out);
}

// round 15
// speedup vs baseline: 1.2797x; 1.0990x over previous
#include <cuda_runtime.h>
#include <cuda_bf16.h>
#include <cstdint>
#include <math.h>

// ---------------------------------------------------------------------------
// CorrelationAdaptor, fully batched: 7 launches.
//   wprep -> transpose_all(+copy) -> xb_convert -> corr_all(bf16, 4px/warp,
//   iy-split 4/4/2/1) -> offset_all -> im2col_all -> gemm_mma (128x64)
// Levels: S={64,32,16,8}, disp={8,8,4,2}, stride={2,1,1,1}
// K2={289,289,81,25}, pad={16,8,4,2}, SP={320,320,96,32}
// Flat pixel space: bases {0, 8192, 10240, 10752}, total 10880.
// NOTE: harness compiles .target sm_100 (no 'a') -> tcgen05 unavailable.
// ---------------------------------------------------------------------------

__device__ float g_xt  [5570560];                        // NHWC x fp32
__device__ __align__(16) unsigned g_xb[2785280];         // NHWC x bf16x2
__device__ float g_corr[3330048];                        // [flat bp][SP]
__device__ float g_off [10880 * 72];                     // [flat p][72]
__device__ __align__(16) unsigned g_colh[10880 * 1152];  // bf16x2 col hi [p][K/2]
__device__ __align__(16) unsigned g_coll[10880 * 1152];  // bf16x2 col lo
__device__ __align__(16) unsigned g_wh  [4 * 256 * 1152];// bf16x2 W hi [l][o][K/2]
__device__ __align__(16) unsigned g_wl  [4 * 256 * 1152];// bf16x2 W lo

__device__ __forceinline__ uint32_t smem_u32(const void* p) {
    uint32_t a;
    asm("{ .reg .u64 t; cvta.to.shared.u64 t, %1; cvt.u32.u64 %0, t; }"
        : "=r"(a) : "l"(p));
    return a;
}
__device__ __forceinline__ float bf_lo(unsigned u) {
    return __uint_as_float(u << 16);
}
__device__ __forceinline__ float bf_hi(unsigned u) {
    return __uint_as_float(u & 0xffff0000u);
}

#define CPA16(dst, src) \
    asm volatile("cp.async.cg.shared.global [%0], [%1], 16;" \
                 :: "r"(dst), "l"(src))
#define CPA_COMMIT() asm volatile("cp.async.commit_group;" ::: "memory")
#define CPA_WAIT1()  asm volatile("cp.async.wait_group 1;" ::: "memory")
#define CPA_WAIT0()  asm volatile("cp.async.wait_group 0;" ::: "memory")

#define LDSM4(r, addr) \
    asm volatile("ldmatrix.sync.aligned.m8n8.x4.shared.b16 {%0,%1,%2,%3}, [%4];" \
                 : "=r"((r)[0]), "=r"((r)[1]), "=r"((r)[2]), "=r"((r)[3]) \
                 : "r"(addr))

#define MMA16816(c, a, b0, b1) \
    asm volatile("mma.sync.aligned.m16n8k16.row.col.f32.bf16.bf16.f32 " \
                 "{%0,%1,%2,%3}, {%4,%5,%6,%7}, {%8,%9}, {%0,%1,%2,%3};" \
                 : "+f"((c)[0]), "+f"((c)[1]), "+f"((c)[2]), "+f"((c)[3]) \
                 : "r"((a)[0]), "r"((a)[1]), "r"((a)[2]), "r"((a)[3]), \
                   "r"(b0), "r"(b1))

// ---------------------------------------------------------------------------
// transpose_all: NCHW -> NHWC fp32 for all levels + x[0] passthrough copy.
// ---------------------------------------------------------------------------
template<int S>
__device__ __forceinline__ void transpose_one(
    int local, const float* __restrict__ x, float* __restrict__ xtb,
    float* __restrict__ outb, float (*t)[33]) {
    constexpr int P = S * S;
    int tb = local & 3;
    int ct = (local >> 2) & 7;
    int pt = local >> 5;
    int p0 = pt * 32, c0 = ct * 32;
    const float* src = x + (size_t)tb * (256 * P);
    float* dst = xtb + (size_t)tb * (256 * P);
    int tx = threadIdx.x;
    bool copy = (tb < 2);
    float* cp = outb + (size_t)tb * (256 * P);
    for (int j = threadIdx.y; j < 32; j += 8) {
        float v = src[(c0 + j) * P + (p0 + tx)];
        t[j][tx] = v;
        if (copy) cp[(c0 + j) * P + (p0 + tx)] = v;
    }
    __syncthreads();
    for (int j = threadIdx.y; j < 32; j += 8)
        dst[(size_t)(p0 + j) * 256 + (c0 + tx)] = t[tx][j];
}

__global__ void transpose_all(const float* __restrict__ x0, const float* __restrict__ x1,
                              const float* __restrict__ x2, const float* __restrict__ x3,
                              float* __restrict__ out) {
    __shared__ float t[32][33];
    int id = blockIdx.x;
    if (id < 4096)      transpose_one<64>(id,        x0, g_xt,           out,           t);
    else if (id < 5120) transpose_one<32>(id - 4096, x1, g_xt + 4194304, out + 4194304, t);
    else if (id < 5376) transpose_one<16>(id - 5120, x2, g_xt + 5242880, out + 5242880, t);
    else                transpose_one< 8>(id - 5376, x3, g_xt + 5505024, out + 5505024, t);
}

// ---------------------------------------------------------------------------
// xb_convert: g_xt fp32 -> g_xb bf16x2 (channel pairs). 10880 x 256 threads.
// ---------------------------------------------------------------------------
__global__ void xb_convert() {
    int i = blockIdx.x * 256 + threadIdx.x;   // [0, 2785280)
    float2 v = *reinterpret_cast<const float2*>(g_xt + 2 * (size_t)i);
    __nv_bfloat16 a = __float2bfloat16_rn(v.x);
    __nv_bfloat16 b = __float2bfloat16_rn(v.y);
    g_xb[i] = ((unsigned)__bfloat16_as_ushort(b) << 16) | __bfloat16_as_ushort(a);
}

// ---------------------------------------------------------------------------
// Weight prep: w_adapt[o][C][ky][kx] -> bf16 hi/lo in [l][o][K], K = k*256+C.
// ---------------------------------------------------------------------------
__global__ void wprep_kernel(const float* __restrict__ w0, const float* __restrict__ w1,
                             const float* __restrict__ w2, const float* __restrict__ w3) {
    int l = blockIdx.y;
    const float* src = (l == 0) ? w0 : (l == 1) ? w1 : (l == 2) ? w2 : w3;
    int idx = blockIdx.x * 256 + threadIdx.x;     // [0, 294912)
    int o = idx / 1152, j = idx - o * 1152;
    int K0 = 2 * j, K1 = K0 + 1;
    int k0 = K0 >> 8, C0 = K0 & 255;
    int k1 = K1 >> 8, C1 = K1 & 255;
    float a = src[o * 2304 + C0 * 9 + k0];
    float b = src[o * 2304 + C1 * 9 + k1];
    __nv_bfloat16 ah = __float2bfloat16_rn(a);
    __nv_bfloat16 bh = __float2bfloat16_rn(b);
    __nv_bfloat16 al = __float2bfloat16_rn(a - __bfloat162float(ah));
    __nv_bfloat16 bl = __float2bfloat16_rn(b - __bfloat162float(bh));
    size_t d = (size_t)l * 294912 + idx;
    g_wh[d] = ((unsigned)__bfloat16_as_ushort(bh) << 16) | __bfloat16_as_ushort(ah);
    g_wl[d] = ((unsigned)__bfloat16_as_ushort(bl) << 16) | __bfloat16_as_ushort(al);
}

// ---------------------------------------------------------------------------
// corr_all v3: warp = (4-pixel group) x (iy-range). 8 lanes/pixel, 32 ch/lane.
// iy split 4-way (L0/L1), 2-way (L2), 1 (L3) -> 10528 warps total for
// latency hiding (v2 had only 2720 -> occ 27%, latency-bound).
// ---------------------------------------------------------------------------
template<int S, int D, int ST, int PD, int K2, int SP>
__device__ __forceinline__ void corr4(int locbase, int lane, int iy0, int iy1,
                                      bool dopad,
                                      const unsigned* __restrict__ xbB,
                                      float* __restrict__ corrb) {
    constexpr int P = S * S;
    int p = lane >> 3, cl = lane & 7;
    int wloc = locbase + p;
    int b = wloc / P, pix = wloc - b * P;
    int h = pix / S, w = pix - h * S;

    const uint4* f1p = reinterpret_cast<const uint4*>(
        xbB + ((size_t)(2 + b) * P + pix) * 128 + cl * 16);
    uint4 a0 = f1p[0], a1 = f1p[1], a2 = f1p[2], a3 = f1p[3];
    unsigned pk[16] = {a0.x, a0.y, a0.z, a0.w, a1.x, a1.y, a1.z, a1.w,
                       a2.x, a2.y, a2.z, a2.w, a3.x, a3.y, a3.z, a3.w};
    float f1v[32];
#pragma unroll
    for (int i = 0; i < 16; i++) {
        f1v[2 * i]     = bf_lo(pk[i]);
        f1v[2 * i + 1] = bf_hi(pk[i]);
    }

    const unsigned* f2base = xbB + (size_t)b * P * 128;
    float* cw = corrb + (size_t)wloc * SP;

    for (int iy = iy0; iy < iy1; iy++) {
        int py = h - PD + iy * ST;
        int s = iy * D;
        for (int ix = 0; ix < D; ix++, s++) {
            int px = w - PD + ix * ST;
            float acc0 = 0.f, acc1 = 0.f;
            if ((unsigned)py < (unsigned)S && (unsigned)px < (unsigned)S) {
                const uint4* f2p = reinterpret_cast<const uint4*>(
                    f2base + ((size_t)py * S + px) * 128 + cl * 16);
                uint4 q0 = f2p[0], q1 = f2p[1], q2 = f2p[2], q3 = f2p[3];
                unsigned qk[16] = {q0.x, q0.y, q0.z, q0.w, q1.x, q1.y, q1.z, q1.w,
                                   q2.x, q2.y, q2.z, q2.w, q3.x, q3.y, q3.z, q3.w};
#pragma unroll
                for (int i = 0; i < 16; i += 2) {
                    acc0 = fmaf(f1v[2 * i],     bf_lo(qk[i]),     acc0);
                    acc0 = fmaf(f1v[2 * i + 1], bf_hi(qk[i]),     acc0);
                    acc1 = fmaf(f1v[2 * i + 2], bf_lo(qk[i + 1]), acc1);
                    acc1 = fmaf(f1v[2 * i + 3], bf_hi(qk[i + 1]), acc1);
                }
            }
            float v = acc0 + acc1;
            v += __shfl_xor_sync(0xffffffffu, v, 4);
            v += __shfl_xor_sync(0xffffffffu, v, 2);
            v += __shfl_xor_sync(0xffffffffu, v, 1);
            if (cl == 0) cw[s] = v * (1.f / 256.f);
        }
    }
    if (dopad)
        for (int z = K2 + cl; z < SP; z += 8) cw[z] = 0.f;
}

// Warp map (10528 warps, 1316 blocks x 8 warps):
//   [0,8192):      L0, group = gw>>2 (4 px), split = gw&3, iy {0-5,5-9,9-13,13-17}
//   [8192,10240):  L1, same split scheme
//   [10240,10496): L2, group = g>>1, split = g&1, iy {0-5,5-9}
//   [10496,10528): L3, group = g, iy {0-5}
__global__ void __launch_bounds__(256) corr_all() {
    int gw = (blockIdx.x * blockDim.x + threadIdx.x) >> 5;
    int lane = threadIdx.x & 31;
    if (gw < 8192) {
        int grp = gw >> 2, sp = gw & 3;
        int iy0 = sp ? (1 + sp * 4) : 0;
        int iy1 = 5 + sp * 4;
        corr4<64, 17, 2, 16, 289, 320>(grp * 4, lane, iy0, iy1, sp == 3,
                                       g_xb, g_corr);
    } else if (gw < 10240) {
        int g2 = gw - 8192;
        int grp = g2 >> 2, sp = g2 & 3;
        int iy0 = sp ? (1 + sp * 4) : 0;
        int iy1 = 5 + sp * 4;
        corr4<32, 17, 1, 8, 289, 320>(grp * 4, lane, iy0, iy1, sp == 3,
                                      g_xb + 2097152, g_corr + 2621440);
    } else if (gw < 10496) {
        int g2 = gw - 10240;
        int grp = g2 >> 1, sp = g2 & 1;
        int iy0 = sp ? 5 : 0;
        int iy1 = sp ? 9 : 5;
        corr4<16, 9, 1, 4, 81, 96>(grp * 4, lane, iy0, iy1, sp == 1,
                                   g_xb + 2621440, g_corr + 3276800);
    } else {
        int g2 = gw - 10496;
        corr4<8, 5, 1, 2, 25, 32>(g2 * 4, lane, 0, 5, true,
                                  g_xb + 2752512, g_corr + 3325952);
    }
}

// ---------------------------------------------------------------------------
// offset_all: block = 64 flat pixels x 72 outputs, 288 threads, 170 blocks.
// ---------------------------------------------------------------------------
template<int K2, int SP>
__device__ __forceinline__ void offset_one(const float* __restrict__ w_off,
                                           const float* __restrict__ corrb,
                                           int local, int flatpb,
                                           float (*Ws)[73], float (*Cs)[65]) {
    int tid = threadIdx.x;
    int og = tid >> 4, pg = tid & 15;
    int pb = local * 64;

    float acc[4][4];
#pragma unroll
    for (int j = 0; j < 4; j++)
#pragma unroll
        for (int i = 0; i < 4; i++) acc[j][i] = 0.f;

    int wo = tid >> 2;
    int ws0 = (tid & 3) * 8;

    for (int cs = 0; cs < SP; cs += 32) {
#pragma unroll
        for (int u = 0; u < 8; u++) {
            int s = ws0 + u;
            int gs = cs + s;
            Ws[s][wo] = (gs < K2) ? w_off[(size_t)wo * K2 + gs] : 0.f;
        }
        for (int idx = tid; idx < 512; idx += 288) {
            int px = idx & 63, s4 = idx >> 6;
            float4 v = *reinterpret_cast<const float4*>(
                corrb + (size_t)(pb + px) * SP + cs + s4 * 4);
            Cs[s4 * 4 + 0][px] = v.x;
            Cs[s4 * 4 + 1][px] = v.y;
            Cs[s4 * 4 + 2][px] = v.z;
            Cs[s4 * 4 + 3][px] = v.w;
        }
        __syncthreads();
#pragma unroll 4
        for (int s = 0; s < 32; s++) {
            float c0 = Cs[s][pg];
            float c1 = Cs[s][pg + 16];
            float c2 = Cs[s][pg + 32];
            float c3 = Cs[s][pg + 48];
#pragma unroll
            for (int j = 0; j < 4; j++) {
                float wv = Ws[s][og * 4 + j];
                acc[j][0] = fmaf(wv, c0, acc[j][0]);
                acc[j][1] = fmaf(wv, c1, acc[j][1]);
                acc[j][2] = fmaf(wv, c2, acc[j][2]);
                acc[j][3] = fmaf(wv, c3, acc[j][3]);
            }
        }
        __syncthreads();
    }
#pragma unroll
    for (int i = 0; i < 4; i++)
#pragma unroll
        for (int j = 0; j < 4; j++)
            g_off[(size_t)(flatpb + pg + 16 * i) * 72 + og * 4 + j] = acc[j][i];
}

__global__ void __launch_bounds__(288) offset_all(
    const float* __restrict__ wo0, const float* __restrict__ wo1,
    const float* __restrict__ wo2, const float* __restrict__ wo3) {
    __shared__ float Ws[32][73];
    __shared__ float Cs[32][65];
    int id = blockIdx.x;
    if (id < 128)      offset_one<289, 320>(wo0, g_corr,           id,       id * 64,                 Ws, Cs);
    else if (id < 160) offset_one<289, 320>(wo1, g_corr + 2621440, id - 128, 8192  + (id - 128) * 64, Ws, Cs);
    else if (id < 168) offset_one< 81,  96>(wo2, g_corr + 3276800, id - 160, 10240 + (id - 160) * 64, Ws, Cs);
    else               offset_one< 25,  32>(wo3, g_corr + 3325952, id - 168, 10752 + (id - 168) * 64, Ws, Cs);
}

// ---------------------------------------------------------------------------
// im2col_all: warp per flat pixel; bilinear -> bf16 hi/lo [p][K], K=k*256+C.
// ---------------------------------------------------------------------------
template<int S>
__device__ __forceinline__ void im2col_one(int wflat, int wloc, int lane,
                                           const float* __restrict__ xtb) {
    constexpr int P = S * S;
    int b = wloc / P, pix = wloc - b * P;
    int h = pix / S, w = pix - h * S;

    const float* op = g_off + (size_t)wflat * 72;
    const float* xi = xtb + (size_t)(2 + b) * P * 256;
    size_t rowb = (size_t)wflat * 1152;

    for (int q = 0; q < 36; q++) {
        int g = q / 9, k = q - g * 9;
        int ky = k / 3, kx = k - ky * 3;
        float fy = (float)(h + ky - 1) + op[q * 2];
        float fx = (float)(w + kx - 1) + op[q * 2 + 1];
        float fy0 = floorf(fy), fx0 = floorf(fx);
        float wy = fy - fy0, wx = fx - fx0;
        int y0 = (int)fy0, x0 = (int)fx0;
        float w00 = (1.f - wy) * (1.f - wx);
        float w01 = (1.f - wy) * wx;
        float w10 = wy * (1.f - wx);
        float w11 = wy * wx;
        bool vy0 = (unsigned)y0 < (unsigned)S, vy1 = (unsigned)(y0 + 1) < (unsigned)S;
        bool vx0 = (unsigned)x0 < (unsigned)S, vx1 = (unsigned)(x0 + 1) < (unsigned)S;
        bool v00 = vy0 && vx0, v01 = vy0 && vx1, v10 = vy1 && vx0, v11 = vy1 && vx1;

        const float* xc = xi + g * 64 + lane * 2;
        int i00 = (y0 * S + x0) * 256;
        float a0 = 0.f, a1 = 0.f;
        if (v00) { float2 u = *(const float2*)(xc + i00);
                   a0 += w00 * u.x; a1 += w00 * u.y; }
        if (v01) { float2 u = *(const float2*)(xc + i00 + 256);
                   a0 += w01 * u.x; a1 += w01 * u.y; }
        if (v10) { float2 u = *(const float2*)(xc + i00 + S * 256);
                   a0 += w10 * u.x; a1 += w10 * u.y; }
        if (v11) { float2 u = *(const float2*)(xc + i00 + S * 256 + 256);
                   a0 += w11 * u.x; a1 += w11 * u.y; }

        __nv_bfloat16 h0 = __float2bfloat16_rn(a0);
        __nv_bfloat16 h1 = __float2bfloat16_rn(a1);
        __nv_bfloat16 l0 = __float2bfloat16_rn(a0 - __bfloat162float(h0));
        __nv_bfloat16 l1 = __float2bfloat16_rn(a1 - __bfloat162float(h1));
        size_t d = rowb + k * 128 + g * 32 + lane;
        g_colh[d] = ((unsigned)__bfloat16_as_ushort(h1) << 16) | __bfloat16_as_ushort(h0);
        g_coll[d] = ((unsigned)__bfloat16_as_ushort(l1) << 16) | __bfloat16_as_ushort(l0);
    }
}

__global__ void im2col_all() {
    int w = (blockIdx.x * blockDim.x + threadIdx.x) >> 5;
    int lane = threadIdx.x & 31;
    if (w < 8192)       im2col_one<64>(w, w,         lane, g_xt);
    else if (w < 10240) im2col_one<32>(w, w - 8192,  lane, g_xt + 4194304);
    else if (w < 10752) im2col_one<16>(w, w - 10240, lane, g_xt + 5242880);
    else                im2col_one< 8>(w, w - 10752, lane, g_xt + 5505024);
}

// ---------------------------------------------------------------------------
// mma.sync bf16 GEMM, 3-term split. 128(M) x 64(N) CTA, 8 warps (32x32).
// grid (170, 2), block 256.
// ---------------------------------------------------------------------------
#define ST_SIZE 55296
#define OFF_AH  0
#define OFF_AL  18432
#define OFF_BH  36864
#define OFF_BL  46080
#define GEMM_SMEM 110592

__global__ void __launch_bounds__(256) gemm_mma(float* __restrict__ out) {
    extern __shared__ __align__(128) char smem[];
    uint32_t sb = smem_u32(smem);
    int tid = threadIdx.x;
    int lane = tid & 31, warp = tid >> 5;
    int warp_m = warp & 3, warp_n = warp >> 2;   // 4 x 2 warps

    int t = blockIdx.x, m0 = blockIdx.y * 128;
    int L, f, HW, OB, PBL;
    if (t < 128)      { L = 0; f = t * 64;         HW = 4096; OB = 0;       PBL = 0;     }
    else if (t < 160) { L = 1; f = (t - 128) * 64; HW = 1024; OB = 4194304; PBL = 8192;  }
    else if (t < 168) { L = 2; f = (t - 160) * 64; HW = 256;  OB = 5242880; PBL = 10240; }
    else              { L = 3; f = (t - 168) * 64; HW = 64;   OB = 5505024; PBL = 10752; }
    int p0 = PBL + f;
    int b = f / HW, pix = f - b * HW;

    const unsigned* GAh = g_wh + (size_t)(L * 256 + m0) * 1152;
    const unsigned* GAl = g_wl + (size_t)(L * 256 + m0) * 1152;
    const unsigned* GBh = g_colh + (size_t)p0 * 1152;
    const unsigned* GBl = g_coll + (size_t)p0 * 1152;

    auto stage = [&](int ci, int buf) {
        uint32_t base = sb + buf * ST_SIZE;
        int kc = ci * 32;
#pragma unroll
        for (int i = 0; i < 4; i++) {
            int u = i * 256 + tid;
            int r = u >> 3, c = u & 7;
            uint32_t so = (uint32_t)(r * 144 + c * 16);
            CPA16(base + OFF_AH + so, GAh + (size_t)r * 1152 + kc + c * 4);
            CPA16(base + OFF_AL + so, GAl + (size_t)r * 1152 + kc + c * 4);
        }
#pragma unroll
        for (int i = 0; i < 2; i++) {
            int u = i * 256 + tid;
            int r = u >> 3, c = u & 7;
            uint32_t so = (uint32_t)(r * 144 + c * 16);
            CPA16(base + OFF_BH + so, GBh + (size_t)r * 1152 + kc + c * 4);
            CPA16(base + OFF_BL + so, GBl + (size_t)r * 1152 + kc + c * 4);
        }
    };

    float acc[2][4][4];
#pragma unroll
    for (int am = 0; am < 2; am++)
#pragma unroll
        for (int an = 0; an < 4; an++)
#pragma unroll
            for (int i = 0; i < 4; i++) acc[am][an][i] = 0.f;

    uint32_t a_row = (uint32_t)(warp_m * 32 + (lane & 15));
    uint32_t a_koff = (uint32_t)((lane >> 4) * 16);
    uint32_t b_row = (uint32_t)(warp_n * 32 + (lane & 7) + ((lane >> 4) << 3));
    uint32_t b_koff = (uint32_t)(((lane >> 3) & 1) * 16);

    stage(0, 0);
    CPA_COMMIT();

    for (int ci = 0; ci < 36; ci++) {
        if (ci + 1 < 36) {
            stage(ci + 1, (ci + 1) & 1);
            CPA_COMMIT();
            CPA_WAIT1();
        } else {
            CPA_WAIT0();
        }
        __syncthreads();
        uint32_t base = sb + (ci & 1) * ST_SIZE;
#pragma unroll
        for (int ks = 0; ks < 4; ks++) {
            uint32_t ao = a_row * 144 + (uint32_t)(ks * 32) + a_koff;
            uint32_t bo = b_row * 144 + (uint32_t)(ks * 32) + b_koff;
            uint32_t ah0[4], ah1[4], al0[4], al1[4];
            uint32_t bh0[4], bh1[4], bl0[4], bl1[4];
            LDSM4(ah0, base + OFF_AH + ao);
            LDSM4(ah1, base + OFF_AH + ao + 16 * 144);
            LDSM4(al0, base + OFF_AL + ao);
            LDSM4(al1, base + OFF_AL + ao + 16 * 144);
            LDSM4(bh0, base + OFF_BH + bo);
            LDSM4(bh1, base + OFF_BH + bo + 16 * 144);
            LDSM4(bl0, base + OFF_BL + bo);
            LDSM4(bl1, base + OFF_BL + bo + 16 * 144);

            MMA16816(acc[0][0], ah0, bh0[0], bh0[1]);
            MMA16816(acc[0][1], ah0, bh0[2], bh0[3]);
            MMA16816(acc[0][2], ah0, bh1[0], bh1[1]);
            MMA16816(acc[0][3], ah0, bh1[2], bh1[3]);
            MMA16816(acc[1][0], ah1, bh0[0], bh0[1]);
            MMA16816(acc[1][1], ah1, bh0[2], bh0[3]);
            MMA16816(acc[1][2], ah1, bh1[0], bh1[1]);
            MMA16816(acc[1][3], ah1, bh1[2], bh1[3]);

            MMA16816(acc[0][0], ah0, bl0[0], bl0[1]);
            MMA16816(acc[0][1], ah0, bl0[2], bl0[3]);
            MMA16816(acc[0][2], ah0, bl1[0], bl1[1]);
            MMA16816(acc[0][3], ah0, bl1[2], bl1[3]);
            MMA16816(acc[1][0], ah1, bl0[0], bl0[1]);
            MMA16816(acc[1][1], ah1, bl0[2], bl0[3]);
            MMA16816(acc[1][2], ah1, bl1[0], bl1[1]);
            MMA16816(acc[1][3], ah1, bl1[2], bl1[3]);

            MMA16816(acc[0][0], al0, bh0[0], bh0[1]);
            MMA16816(acc[0][1], al0, bh0[2], bh0[3]);
            MMA16816(acc[0][2], al0, bh1[0], bh1[1]);
            MMA16816(acc[0][3], al0, bh1[2], bh1[3]);
            MMA16816(acc[1][0], al1, bh0[0], bh0[1]);
            MMA16816(acc[1][1], al1, bh0[2], bh0[3]);
            MMA16816(acc[1][2], al1, bh1[0], bh1[1]);
            MMA16816(acc[1][3], al1, bh1[2], bh1[3]);
        }
        __syncthreads();
    }

    float* Ob = out + OB + ((size_t)(2 + b) * 256) * HW + pix;
#pragma unroll
    for (int am = 0; am < 2; am++) {
        int o = m0 + warp_m * 32 + am * 16 + (lane >> 2);
#pragma unroll
        for (int an = 0; an < 4; an++) {
            int c = warp_n * 32 + an * 8 + (lane & 3) * 2;
            float2 v0 = make_float2(fmaxf(acc[am][an][0], 0.f),
                                    fmaxf(acc[am][an][1], 0.f));
            float2 v1 = make_float2(fmaxf(acc[am][an][2], 0.f),
                                    fmaxf(acc[am][an][3], 0.f));
            *reinterpret_cast<float2*>(Ob + (size_t)o * HW + c) = v0;
            *reinterpret_cast<float2*>(Ob + (size_t)(o + 8) * HW + c) = v1;
        }
    }
}

extern "C" void kernel_launch(void* const* d_in, const int* in_sizes, int n_in,
                              void* d_out, int out_size) {
    // Runtime input classification by element count (metadata interleaves
    // w_off{i}/w_adapt{i} — do NOT trust signature order).
    const float* xs[4]   = {0, 0, 0, 0};
    const float* wofs[4] = {0, 0, 0, 0};
    const float* wads[4] = {0, 0, 0, 0};
    int n_adapt = 0, n_off_big = 0;
    for (int i = 0; i < n_in; i++) {
        const float* p = (const float*)d_in[i];
        switch (in_sizes[i]) {
            case 4194304: xs[0] = p; break;
            case 1048576: xs[1] = p; break;
            case 262144:  xs[2] = p; break;
            case 65536:   xs[3] = p; break;
            case 589824:  wads[n_adapt++] = p; break;
            case 20808:   wofs[n_off_big++] = p; break;
            case 5832:    wofs[2] = p; break;
            case 1800:    wofs[3] = p; break;
            default: break;
        }
    }
    float* out = (float*)d_out;

    cudaFuncSetAttribute(gemm_mma, cudaFuncAttributeMaxDynamicSharedMemorySize,
                         GEMM_SMEM);

    wprep_kernel<<<dim3(1152, 4), 256>>>(wads[0], wads[1], wads[2], wads[3]);
    transpose_all<<<5440, dim3(32, 8)>>>(xs[0], xs[1], xs[2], xs[3], out);
    xb_convert<<<10880, 256>>>();
    corr_all<<<1316, 256>>>();
    offset_all<<<170, 288>>>(wofs[0], wofs[1], wofs[2], wofs[3]);
    im2col_all<<<1360, 256>>>();
    gemm_mma<<<dim3(170, 2), 256, GEMM_SMEM>>>(out);
}